// round 16
// baseline (speedup 1.0000x reference)
#include <cuda_runtime.h>
#include <cstdint>

#define BB 32
#define TT 2048
#define FF 128
#define HH 512

// 128 MB scratch each
__device__ float g_pre[BB * TT * HH];    // pre[b][t][h] = x W_ih^T + b_ih + b_hh
__device__ float g_hout[BB * TT * HH];   // h(t) per batch (frozen past len)
__device__ float g_v[HH];
__device__ float g_c;

// ---------------------------------------------------------------------------
// helpers
// ---------------------------------------------------------------------------
__device__ __forceinline__ uint32_t smem_u32(const void* p) {
    uint32_t a;
    asm("{ .reg .u64 t; cvta.to.shared.u64 t, %1; cvt.u32.u64 %0, t; }" : "=r"(a) : "l"(p));
    return a;
}
__device__ __forceinline__ uint32_t ctarank() {
    uint32_t r; asm("mov.u32 %0, %%cluster_ctarank;" : "=r"(r)); return r;
}
__device__ __forceinline__ uint32_t mapa_u32(uint32_t a, uint32_t r) {
    uint32_t o; asm("mapa.shared::cluster.u32 %0, %1, %2;" : "=r"(o) : "r"(a), "r"(r)); return o;
}
__device__ __forceinline__ void cluster_sync_() {
    asm volatile("barrier.cluster.arrive.aligned;" ::: "memory");
    asm volatile("barrier.cluster.wait.aligned;" ::: "memory");
}
__device__ __forceinline__ void fma2(unsigned long long& acc, unsigned long long a,
                                     unsigned long long b) {
    asm("fma.rn.f32x2 %0, %1, %2, %0;" : "+l"(acc) : "l"(a), "l"(b));
}
__device__ __forceinline__ float hsum2(unsigned long long a) {
    float lo = __uint_as_float((unsigned)(a & 0xffffffffull));
    float hi = __uint_as_float((unsigned)(a >> 32));
    return lo + hi;
}
__device__ __forceinline__ float ftanh(float x) {
    float e = __expf(2.0f * x);
    return 1.0f - __fdividef(2.0f, e + 1.0f);
}
__device__ __forceinline__ void mbar_init(uint32_t a, uint32_t cnt) {
    asm volatile("mbarrier.init.shared.b64 [%0], %1;" :: "r"(a), "r"(cnt) : "memory");
}
__device__ __forceinline__ void mbar_arrive_expect(uint32_t a, uint32_t tx) {
    asm volatile("mbarrier.arrive.expect_tx.shared.b64 _, [%0], %1;" :: "r"(a), "r"(tx) : "memory");
}
__device__ __forceinline__ void mbar_wait(uint32_t a, uint32_t parity) {
    asm volatile(
        "{\n\t.reg .pred P;\n"
        "W_%=:\n\t"
        "mbarrier.try_wait.parity.acquire.cluster.shared::cta.b64 P, [%0], %1, 0x989680;\n\t"
        "@!P bra W_%=;\n\t"
        "}" :: "r"(a), "r"(parity) : "memory");
}
// remote DSMEM 16B store with tx-counted completion on the peer's mbarrier
__device__ __forceinline__ void st_async16(uint32_t raddr, float a, float b, float c, float d,
                                           uint32_t rmbar) {
    asm volatile(
        "st.async.shared::cluster.mbarrier::complete_tx::bytes.v4.b32 [%0], {%1,%2,%3,%4}, [%5];"
        :: "r"(raddr), "r"(__float_as_uint(a)), "r"(__float_as_uint(b)),
           "r"(__float_as_uint(c)), "r"(__float_as_uint(d)), "r"(rmbar) : "memory");
}

// ---------------------------------------------------------------------------
// v = W2 @ W1 (R^512), c = b2 + W2.b1 ; also zero the count outputs
// ---------------------------------------------------------------------------
__global__ void vc_kernel(const float* __restrict__ W1, const float* __restrict__ b1,
                          const float* __restrict__ W2, const float* __restrict__ b2,
                          float* __restrict__ out) {
    __shared__ float w2s[FF];
    int tid = threadIdx.x;
    if (tid < FF) w2s[tid] = W2[tid];
    if (tid < BB) out[tid] = 0.f;
    __syncthreads();
    if (tid < HH) {
        float s = 0.f;
#pragma unroll 16
        for (int f = 0; f < FF; ++f) s = fmaf(w2s[f], W1[f * HH + tid], s);
        g_v[tid] = s;
    }
    if (tid == 0) {
        float s = b2[0];
        for (int f = 0; f < FF; ++f) s = fmaf(w2s[f], b1[f], s);
        g_c = s;
    }
}

// ---------------------------------------------------------------------------
// Input projection GEMM: [B*T,128] @ [128,512]^T + bias -> g_pre.
// ---------------------------------------------------------------------------
__global__ void __launch_bounds__(256) pre_gemm(const float* __restrict__ x,
                                                const float* __restrict__ Wih,
                                                const float* __restrict__ bih,
                                                const float* __restrict__ bhh) {
    __shared__ float xsT[32][68];
    __shared__ float wsT[32][68];
    const int tid = threadIdx.x;
    const int tx = tid & 15, ty = tid >> 4;
    const int m0 = blockIdx.y << 6;
    const int n0 = blockIdx.x << 6;
    float acc[4][4] = {};
    for (int k0 = 0; k0 < FF; k0 += 32) {
#pragma unroll
        for (int i = 0; i < 8; ++i) {
            int e = (i << 8) + tid;
            int r = e >> 5, cc = e & 31;
            xsT[cc][r] = x[(size_t)(m0 + r) * FF + k0 + cc];
            wsT[cc][r] = Wih[(size_t)(n0 + r) * FF + k0 + cc];
        }
        __syncthreads();
#pragma unroll
        for (int kk = 0; kk < 32; ++kk) {
            float4 a = *(const float4*)&xsT[kk][ty << 2];
            float4 b = *(const float4*)&wsT[kk][tx << 2];
            acc[0][0] = fmaf(a.x, b.x, acc[0][0]); acc[0][1] = fmaf(a.x, b.y, acc[0][1]);
            acc[0][2] = fmaf(a.x, b.z, acc[0][2]); acc[0][3] = fmaf(a.x, b.w, acc[0][3]);
            acc[1][0] = fmaf(a.y, b.x, acc[1][0]); acc[1][1] = fmaf(a.y, b.y, acc[1][1]);
            acc[1][2] = fmaf(a.y, b.z, acc[1][2]); acc[1][3] = fmaf(a.y, b.w, acc[1][3]);
            acc[2][0] = fmaf(a.z, b.x, acc[2][0]); acc[2][1] = fmaf(a.z, b.y, acc[2][1]);
            acc[2][2] = fmaf(a.z, b.z, acc[2][2]); acc[2][3] = fmaf(a.z, b.w, acc[2][3]);
            acc[3][0] = fmaf(a.w, b.x, acc[3][0]); acc[3][1] = fmaf(a.w, b.y, acc[3][1]);
            acc[3][2] = fmaf(a.w, b.z, acc[3][2]); acc[3][3] = fmaf(a.w, b.w, acc[3][3]);
        }
        __syncthreads();
    }
    const int n = n0 + (tx << 2);
    float4 bias;
    bias.x = bih[n + 0] + bhh[n + 0];
    bias.y = bih[n + 1] + bhh[n + 1];
    bias.z = bih[n + 2] + bhh[n + 2];
    bias.w = bih[n + 3] + bhh[n + 3];
#pragma unroll
    for (int i = 0; i < 4; ++i) {
        int m = m0 + (ty << 2) + i;
        float4 o;
        o.x = acc[i][0] + bias.x;
        o.y = acc[i][1] + bias.y;
        o.z = acc[i][2] + bias.z;
        o.w = acc[i][3] + bias.w;
        *(float4*)&g_pre[(size_t)m * HH + n] = o;
    }
}

// ---------------------------------------------------------------------------
// Persistent recurrence with PER-SOURCE mbarriers (8 per buffer, 24 total).
// Key dataflow fact: thread (r2,c) reads only h rows [64c,64c+64) — produced
// entirely by CTA c. So each thread waits ONLY on mbar[buf][c], and incoming
// tx-accounting serializes on 8 independent mbar words (32 msgs each) instead
// of one word with 256 msgs — ~8x less serialization before the parity flips.
// Transport identical to R15: one st.async.v4 (16B, 4 packed rows) per thread,
// batch0 sends fly under batch1 compute. Triple-buffered; no CTA barrier.
// ---------------------------------------------------------------------------
#define SLC   68u                // padded floats per 64-col slice
#define HB    544u               // floats per batch vector (8*68)
#define BATB  2176u              // bytes per batch vector
#define BUFB  4352u              // bytes per buffer (2 batches)
#define EXP_SRC 512u             // 32 msgs * 16B per source-mbar per step

__global__ void __launch_bounds__(256, 1) __cluster_dims__(8, 1, 1)
rnn_kernel(const int* __restrict__ lengths, const float* __restrict__ Whh) {
    // h index j lives at (j>>6)*SLC + (j&63)
    __shared__ __align__(16) float hbuf[3][2][HB];
    __shared__ __align__(8) unsigned long long mbars[24];   // [buf][src]

    const int tid = threadIdx.x;
    const uint32_t rank = ctarank();
    const int cl = blockIdx.x >> 3;
    const int b0 = cl * 2, b1 = b0 + 1;
    const int len0 = lengths[b0], len1 = lengths[b1];
    const int tmax = (len0 > len1) ? len0 : len1;

    const int r2 = tid >> 3;         // 0..31 : row-pair index
    const int c  = tid & 7;          // 0..7  : 64-col slice AND source/dest peer
    const int rowA = (int)rank * 64 + 2 * r2;
    const int myb = r2 & 1;          // which batch this thread's v4 message carries
    const int hoff = c * (int)SLC;

    // ---- W_hh rows (2 x 64 cols) -> 64 packed f32x2 regs ----
    unsigned long long wA[32], wB[32];
    {
        const double2* pA = (const double2*)(Whh + (size_t)rowA * HH + 64 * c);
        const double2* pB = (const double2*)(Whh + (size_t)(rowA + 1) * HH + 64 * c);
#pragma unroll
        for (int i = 0; i < 16; ++i) {
            double2 a = pA[i], b = pB[i];
            wA[2 * i]     = __double_as_longlong(a.x);
            wA[2 * i + 1] = __double_as_longlong(a.y);
            wB[2 * i]     = __double_as_longlong(b.x);
            wB[2 * i + 1] = __double_as_longlong(b.y);
        }
    }

    // ---- init: zero buf 0 (both batches), init all 24 mbarriers ----
    {
        float* hz = &hbuf[0][0][0];
        for (int i = tid; i < (int)(2 * HB); i += 256) hz[i] = 0.f;
    }
    const uint32_t mb_local = smem_u32(&mbars[0]);
    if (tid == 0) {
#pragma unroll
        for (int k = 0; k < 24; ++k) mbar_init(mb_local + (uint32_t)k * 8u, 1);
    }
    __syncthreads();
    cluster_sync_();                 // init + zero visible cluster-wide
    if (tid == 0) {                  // arm all 24 (3 buffers x 8 sources)
#pragma unroll
        for (int k = 0; k < 24; ++k) mbar_arrive_expect(mb_local + (uint32_t)k * 8u, EXP_SRC);
    }

    // remote destinations: this thread's 4-row pack (rows 4k..4k+3, k=r2>>1,
    // batch myb) lands at peer c, float index rank*68+4k, batch region myb;
    // it signals peer c's mbar[buf][src=rank].
    const uint32_t dst_off = (rank * SLC + 4u * (uint32_t)(r2 >> 1)) * 4u + (uint32_t)myb * BATB;
    const uint32_t peer_h  = mapa_u32(smem_u32(&hbuf[0][0][0]), (uint32_t)c) + dst_off;
    const uint32_t peer_mb = mapa_u32(mb_local, (uint32_t)c) + rank * 8u;   // + buf*64

    const float* pb0 = g_pre + (size_t)b0 * TT * HH;
    const float* pb1 = g_pre + (size_t)b1 * TT * HH;

    float2 hr0 = {0.f, 0.f};          // frozen h for our 2 rows, batch 0
    float2 hr1 = {0.f, 0.f};          // batch 1
    int parbits = 0;                  // parity of buffer k in bit k
    int p3 = 0;

    float2 pc0 = *(const float2*)(pb0 + rowA);
    float2 pc1 = *(const float2*)(pb1 + rowA);

    for (int t = 0; t <= tmax; ++t) {
        const int q3 = (p3 == 2) ? 0 : p3 + 1;

        if (t > 0) {                 // consume source c's writes from step t-1
            mbar_wait(mb_local + ((uint32_t)p3 * 8u + (uint32_t)c) * 8u,
                      (uint32_t)((parbits >> p3) & 1));
            parbits ^= 1 << p3;
            // re-arm: thread tid (=c, r2=0) owns source-mbar [p3][tid]
            if (tid < 8)
                mbar_arrive_expect(mb_local + ((uint32_t)p3 * 8u + (uint32_t)tid) * 8u, EXP_SRC);
        }

        if (t < tmax) {
            const int tn = (t + 1 < tmax) ? (t + 1) : t;
            const uint32_t dst = peer_h + (uint32_t)q3 * BUFB;
            const uint32_t dmb = peer_mb + (uint32_t)q3 * 64u;

            // ======== batch 0: compute then send (messages fly under batch 1) ========
            {
                float2 pn0 = *(const float2*)(pb0 + (size_t)tn * HH + rowA);
                const ulonglong2* h0 = (const ulonglong2*)&hbuf[p3][0][hoff];
                unsigned long long aA = 0ull, aB = 0ull;
#pragma unroll
                for (int i = 0; i < 16; ++i) {
                    ulonglong2 x = h0[i];
                    fma2(aA, wA[2 * i], x.x); fma2(aA, wA[2 * i + 1], x.y);
                    fma2(aB, wB[2 * i], x.x); fma2(aB, wB[2 * i + 1], x.y);
                }
                float sA = hsum2(aA), sB = hsum2(aB);
#pragma unroll
                for (int m = 1; m < 8; m <<= 1) {
                    sA += __shfl_xor_sync(0xffffffffu, sA, m);
                    sB += __shfl_xor_sync(0xffffffffu, sB, m);
                }
                if (t < len0) { hr0.x = ftanh(pc0.x + sA); hr0.y = ftanh(pc0.y + sB); }

                // pack 4 contiguous rows (partner pair lives at r2^1 = xor-8 lane)
                float ex = __shfl_xor_sync(0xffffffffu, hr0.x, 8);
                float ey = __shfl_xor_sync(0xffffffffu, hr0.y, 8);
                if (myb == 0)
                    st_async16(dst, hr0.x, hr0.y, ex, ey, dmb);

                if (c == 0)
                    *(float2*)(g_hout + (size_t)b0 * TT * HH + (size_t)t * HH + rowA) = hr0;
                pc0 = pn0;
            }

            // ======== batch 1: compute then send ========
            {
                float2 pn1 = *(const float2*)(pb1 + (size_t)tn * HH + rowA);
                const ulonglong2* h1 = (const ulonglong2*)&hbuf[p3][1][hoff];
                unsigned long long aA = 0ull, aB = 0ull;
#pragma unroll
                for (int i = 0; i < 16; ++i) {
                    ulonglong2 x = h1[i];
                    fma2(aA, wA[2 * i], x.x); fma2(aA, wA[2 * i + 1], x.y);
                    fma2(aB, wB[2 * i], x.x); fma2(aB, wB[2 * i + 1], x.y);
                }
                float sA = hsum2(aA), sB = hsum2(aB);
#pragma unroll
                for (int m = 1; m < 8; m <<= 1) {
                    sA += __shfl_xor_sync(0xffffffffu, sA, m);
                    sB += __shfl_xor_sync(0xffffffffu, sB, m);
                }
                if (t < len1) { hr1.x = ftanh(pc1.x + sA); hr1.y = ftanh(pc1.y + sB); }

                float ex = __shfl_xor_sync(0xffffffffu, hr1.x, 8);
                float ey = __shfl_xor_sync(0xffffffffu, hr1.y, 8);
                if (myb == 1)
                    st_async16(dst, ex, ey, hr1.x, hr1.y, dmb);

                if (c == 1)
                    *(float2*)(g_hout + (size_t)b1 * TT * HH + (size_t)t * HH + rowA) = hr1;
                pc1 = pn1;
            }
        }

        p3 = q3;
    }

    cluster_sync_();   // drain in-flight st.async before any CTA exits
}

// ---------------------------------------------------------------------------
// Post-kernel head: counts = sum_t<len (h(t).v + c > 0), h_final = h[len-1].
// grid (4, BB): 4 t-range quarters per batch; counts via atomicAdd (exact ints).
// ---------------------------------------------------------------------------
__global__ void __launch_bounds__(256) count_kernel(const int* __restrict__ lengths,
                                                    float* __restrict__ out, int out_size) {
    const int b = blockIdx.y;
    const int quarter = blockIdx.x;
    const int len = lengths[b];
    const int t0 = quarter * (TT / 4), t1 = t0 + TT / 4;
    const int tid = threadIdx.x, lane = tid & 31, wid = tid >> 5;

    float4 v[4];
#pragma unroll
    for (int i = 0; i < 4; ++i) v[i] = *(const float4*)(g_v + lane * 16 + i * 4);
    const float c = g_c;
    const float* hb = g_hout + (size_t)b * TT * HH;

    const int tend = (t1 < len) ? t1 : len;
    int cnt = 0;
    for (int t = t0 + wid; t < tend; t += 8) {
        const float4* hp = (const float4*)(hb + (size_t)t * HH + lane * 16);
        float d = 0.f;
#pragma unroll
        for (int i = 0; i < 4; ++i) {
            float4 h4 = hp[i];
            d = fmaf(h4.x, v[i].x, d); d = fmaf(h4.y, v[i].y, d);
            d = fmaf(h4.z, v[i].z, d); d = fmaf(h4.w, v[i].w, d);
        }
#pragma unroll
        for (int m = 1; m < 32; m <<= 1) d += __shfl_xor_sync(0xffffffffu, d, m);
        if (lane == 0 && d + c > 0.f) cnt++;
    }
    __shared__ int wcnt[8];
    if (lane == 0) wcnt[wid] = cnt;
    __syncthreads();
    if (tid == 0) {
        int sum = 0;
#pragma unroll
        for (int i = 0; i < 8; ++i) sum += wcnt[i];
        if (sum) atomicAdd(&out[b], (float)sum);
    }

    if (out_size >= BB + BB * HH) {
        const int tf = len - 1;
        if (tf >= t0 && tf < t1) {
            for (int j = tid; j < HH; j += 256)
                out[BB + (size_t)b * HH + j] = hb[(size_t)tf * HH + j];
        }
    }
}

// ---------------------------------------------------------------------------
// launch
// ---------------------------------------------------------------------------
extern "C" void kernel_launch(void* const* d_in, const int* in_sizes, int n_in,
                              void* d_out, int out_size) {
    const float* x     = (const float*)d_in[0];
    const int* lengths = (const int*)d_in[1];
    const float* W_ih  = (const float*)d_in[2];
    const float* W_hh  = (const float*)d_in[3];
    const float* b_ih  = (const float*)d_in[4];
    const float* b_hh  = (const float*)d_in[5];
    const float* W1    = (const float*)d_in[6];
    const float* b1    = (const float*)d_in[7];
    const float* W2    = (const float*)d_in[8];
    const float* b2    = (const float*)d_in[9];
    float* out = (float*)d_out;

    vc_kernel<<<1, 512>>>(W1, b1, W2, b2, out);

    dim3 ggrid(HH / 64, (BB * TT) / 64);   // (8, 1024)
    pre_gemm<<<ggrid, 256>>>(x, W_ih, b_ih, b_hh);

    rnn_kernel<<<128, 256>>>(lengths, W_hh);

    count_kernel<<<dim3(4, BB), 256>>>(lengths, out, out_size);
}